// round 12
// baseline (speedup 1.0000x reference)
#include <cuda_runtime.h>
#include <cuda_fp16.h>
#include <cstdint>

// EdgeNetwork via mma.sync m16n8k16 fp16 error-compensated split.
// H = E@W + b ; messages[g,i] = sum_j relu(H[g, 32i+j]) * s[g,j]
// E = Eh + El, W = Wh + Wl (fp16). H ~= EhWh + EhWl + ElWh.
// R12: merged column-halves -> one 512-thread CTA per 128 edges: E/states staged
// once, float4 flush. Main loop identical to R11 (W+bias in regs, rolled hp).

#define NTHREADS 512

// Pre-split W, fragment-permuted, hi/lo interleaved:
// d_Whl[n*4+q] = { h2(wh[2q][n],wh[2q+1][n]), h2(wh[2q+8][n],wh[2q+9][n]),
//                  h2(wl[2q][n],wl[2q+1][n]), h2(wl[2q+8][n],wl[2q+9][n]) }
__device__ uint4 d_Whl[4096];

__device__ __forceinline__ void split16(float v, __half& hi, __half& lo) {
    hi = __float2half_rn(v);
    lo = __float2half_rn(v - __half2float(hi));
}
__device__ __forceinline__ uint32_t pack_h2(__half a, __half b) {
    __half2 h = __halves2half2(a, b);
    return *reinterpret_cast<uint32_t*>(&h);
}

__global__ void prep_w(const float* __restrict__ W) {
    int idx = blockIdx.x * 256 + threadIdx.x;   // 0..4095 over [n][q]
    int n = idx >> 2, q = idx & 3;
    __half h0, l0, h1, l1, h2v, l2, h3, l3;
    split16(W[(2 * q)     * 1024 + n], h0, l0);
    split16(W[(2 * q + 1) * 1024 + n], h1, l1);
    split16(W[(2 * q + 8) * 1024 + n], h2v, l2);
    split16(W[(2 * q + 9) * 1024 + n], h3, l3);
    d_Whl[idx] = make_uint4(pack_h2(h0, h1), pack_h2(h2v, h3),
                            pack_h2(l0, l1), pack_h2(l2, l3));
}

// D = A*B + D
__device__ __forceinline__ void mma16(float* d, uint32_t a0, uint32_t a1,
                                      uint32_t a2, uint32_t a3,
                                      uint32_t b0, uint32_t b1) {
    asm volatile(
        "mma.sync.aligned.m16n8k16.row.col.f32.f16.f16.f32 "
        "{%0,%1,%2,%3}, {%4,%5,%6,%7}, {%8,%9}, {%0,%1,%2,%3};"
        : "+f"(d[0]), "+f"(d[1]), "+f"(d[2]), "+f"(d[3])
        : "r"(a0), "r"(a1), "r"(a2), "r"(a3), "r"(b0), "r"(b1));
}
// D = A*B + {cx,cy,cx,cy}
__device__ __forceinline__ void mma16c(float* d, uint32_t a0, uint32_t a1,
                                       uint32_t a2, uint32_t a3,
                                       uint32_t b0, uint32_t b1,
                                       float cx, float cy) {
    asm volatile(
        "mma.sync.aligned.m16n8k16.row.col.f32.f16.f16.f32 "
        "{%0,%1,%2,%3}, {%4,%5,%6,%7}, {%8,%9}, {%10,%11,%10,%11};"
        : "=f"(d[0]), "=f"(d[1]), "=f"(d[2]), "=f"(d[3])
        : "r"(a0), "r"(a1), "r"(a2), "r"(a3), "r"(b0), "r"(b1),
          "f"(cx), "f"(cy));
}

__global__ __launch_bounds__(NTHREADS, 1) void edge_net_mma(
    const float* __restrict__ states,
    const float* __restrict__ edges,
    const float* __restrict__ bg,
    float* __restrict__ out)
{
    __shared__ uint4  EHL[128 * 4];          // 8 KB  [row][q]
    __shared__ float2 SP[4 * 128 * 4];       // 16 KB [a][row][q2]
    __shared__ float  OSM[128 * 36];         // 18 KB output stage (pitch 36)

    const int tid = threadIdx.x;
    const int gbase = blockIdx.x * 128;

    const int w = tid >> 5, lane = tid & 31;
    const int g = lane >> 2;                 // groupID: row-in-tile / B-col
    const int q = lane & 3;                  // threadID-in-group

    // ---- Stage + split edges (once for all 16 warps) ----
    {
        const float2* er = (const float2*)(edges + (size_t)gbase * 16);
        int row = tid >> 2, qq = tid & 3;    // 512 items exactly
        float2 v0 = er[row * 8 + qq];
        float2 v1 = er[row * 8 + qq + 4];
        __half h0, l0, h1, l1, h2v, l2, h3, l3;
        split16(v0.x, h0, l0);  split16(v0.y, h1, l1);
        split16(v1.x, h2v, l2); split16(v1.y, h3, l3);
        EHL[tid] = make_uint4(pack_h2(h0, h1), pack_h2(h2v, h3),
                              pack_h2(l0, l1), pack_h2(l2, l3));
    }
    // ---- Stage states: SP[a][row][q2] = {s[row][8a+2q2], s[row][8a+2q2+1]} ----
    {
        const float4* sv = (const float4*)(states + (size_t)gbase * 32);
        #pragma unroll
        for (int k = 0; k < 2; k++) {
            int idx = tid + k * 512;         // 0..1023 over [row][f4]
            int row = idx >> 3, f4 = idx & 7;
            float4 v = sv[idx];
            int a = f4 >> 1, q2 = (f4 & 1) * 2;
            *(float4*)((float*)SP + ((a * 128 + row) * 4 + q2) * 2) = v;
        }
    }
    __syncthreads();

    // ---- W + bias fragments -> registers (after sync: no staging overlap) ----
    uint4 whl[8];
    float2 b2[8];
    #pragma unroll
    for (int ct = 0; ct < 8; ct++) {
        int n = w * 64 + ct * 8 + g;         // w covers all 1024 cols (16 warps)
        whl[ct] = d_Whl[n * 4 + q];
        b2[ct] = *(const float2*)(bg + w * 64 + ct * 8 + 2 * q);
    }

    // ---- Main: 8 rolled steps of 16 rows ----
    #pragma unroll 1
    for (int hp = 0; hp < 8; hp++) {
        const int rb = hp * 16;

        const uint4 aA = EHL[(rb + g) * 4 + q];       // rows g
        const uint4 aB = EHL[(rb + 8 + g) * 4 + q];   // rows g+8

        float mm[2][2] = {{0.f, 0.f}, {0.f, 0.f}};    // [ip][row-half]

        #pragma unroll
        for (int a = 0; a < 4; a++) {
            const float2 s0 = SP[a * 512 + (rb + g) * 4 + q];
            const float2 s1 = SP[a * 512 + (rb + 8 + g) * 4 + q];

            #pragma unroll
            for (int ip = 0; ip < 2; ip++) {
                const int ct = ip * 4 + a;
                float d[4];
                mma16c(d, aA.x, aB.x, aA.y, aB.y, whl[ct].x, whl[ct].y,
                       b2[ct].x, b2[ct].y);
                mma16 (d, aA.x, aB.x, aA.y, aB.y, whl[ct].z, whl[ct].w);
                mma16 (d, aA.z, aB.z, aA.w, aB.w, whl[ct].x, whl[ct].y);

                mm[ip][0] = fmaf(fmaxf(d[0], 0.f), s0.x, mm[ip][0]);
                mm[ip][0] = fmaf(fmaxf(d[1], 0.f), s0.y, mm[ip][0]);
                mm[ip][1] = fmaf(fmaxf(d[2], 0.f), s1.x, mm[ip][1]);
                mm[ip][1] = fmaf(fmaxf(d[3], 0.f), s1.y, mm[ip][1]);
            }
        }

        // ---- Quad reduce, stage to OSM (conflict-free, pitch 36) ----
        #pragma unroll
        for (int ip = 0; ip < 2; ip++) {
            const int il = w * 2 + ip;       // output column 0..31
            float v0 = mm[ip][0], v1 = mm[ip][1];
            v0 += __shfl_xor_sync(0xffffffffu, v0, 1);
            v0 += __shfl_xor_sync(0xffffffffu, v0, 2);
            v1 += __shfl_xor_sync(0xffffffffu, v1, 1);
            v1 += __shfl_xor_sync(0xffffffffu, v1, 2);
            if (q == 0) {
                OSM[(rb + g) * 36 + il] = v0;
                OSM[(rb + 8 + g) * 36 + il] = v1;
            }
        }
    }

    // ---- Coalesced float4 flush ----
    __syncthreads();
    #pragma unroll
    for (int k = 0; k < 2; k++) {
        int idx = tid + k * 512;             // 0..1023 over [row][c4]
        int row = idx >> 3, c4 = idx & 7;
        float4 v = *(const float4*)(OSM + row * 36 + c4 * 4);
        *(float4*)(out + (size_t)(gbase + row) * 32 + c4 * 4) = v;
    }
}

extern "C" void kernel_launch(void* const* d_in, const int* in_sizes, int n_in,
                              void* d_out, int out_size)
{
    const float* states = (const float*)d_in[0];  // [16, 4096, 32]
    const float* edges  = (const float*)d_in[1];  // [16, 4096, 16]
    const float* W      = (const float*)d_in[2];  // [16, 1024]
    const float* b      = (const float*)d_in[3];  // [1024]
    float* out          = (float*)d_out;          // [16, 4096, 32]

    (void)in_sizes; (void)n_in; (void)out_size;

    prep_w<<<16, 256>>>(W);
    edge_net_mma<<<512, NTHREADS>>>(states, edges, b, out);
}

// round 13
// speedup vs baseline: 1.1332x; 1.1332x over previous
#include <cuda_runtime.h>
#include <cuda_fp16.h>
#include <cstdint>

// EdgeNetwork via mma.sync m16n8k16 fp16 error-compensated split.
// H = E@W + b ; messages[g,i] = sum_j relu(H[g, 32i+j]) * s[g,j]
// E = Eh + El, W = Wh + Wl (fp16). H ~= EhWh + EhWl + ElWh.
// R13: R11 base (grid 1024, 2 CTAs/SM, W+bias in regs, rolled hp) with the
// shuffle reduction replaced by STS quad-partials + LDS.128 flush reduce.

#define NTHREADS 256

// dynamic smem offsets (bytes)
#define SM_EHL  0                        // uint4[512]           8 KB
#define SM_SP   8192                     // float2[2048]        16 KB
#define SM_OSM  24576                    // float[128*68]    34816 B
#define SM_TOTAL (24576 + 34816)         // 59392 B/CTA (x2 = 118.7 KB/SM)

// Pre-split W, fragment-permuted, hi/lo interleaved:
// d_Whl[n*4+q] = { h2(wh[2q][n],wh[2q+1][n]), h2(wh[2q+8][n],wh[2q+9][n]),
//                  h2(wl[2q][n],wl[2q+1][n]), h2(wl[2q+8][n],wl[2q+9][n]) }
__device__ uint4 d_Whl[4096];

__device__ __forceinline__ void split16(float v, __half& hi, __half& lo) {
    hi = __float2half_rn(v);
    lo = __float2half_rn(v - __half2float(hi));
}
__device__ __forceinline__ uint32_t pack_h2(__half a, __half b) {
    __half2 h = __halves2half2(a, b);
    return *reinterpret_cast<uint32_t*>(&h);
}

__global__ void prep_w(const float* __restrict__ W) {
    int idx = blockIdx.x * 256 + threadIdx.x;   // 0..4095 over [n][q]
    int n = idx >> 2, q = idx & 3;
    __half h0, l0, h1, l1, h2v, l2, h3, l3;
    split16(W[(2 * q)     * 1024 + n], h0, l0);
    split16(W[(2 * q + 1) * 1024 + n], h1, l1);
    split16(W[(2 * q + 8) * 1024 + n], h2v, l2);
    split16(W[(2 * q + 9) * 1024 + n], h3, l3);
    d_Whl[idx] = make_uint4(pack_h2(h0, h1), pack_h2(h2v, h3),
                            pack_h2(l0, l1), pack_h2(l2, l3));
}

// D = A*B + D
__device__ __forceinline__ void mma16(float* d, uint32_t a0, uint32_t a1,
                                      uint32_t a2, uint32_t a3,
                                      uint32_t b0, uint32_t b1) {
    asm volatile(
        "mma.sync.aligned.m16n8k16.row.col.f32.f16.f16.f32 "
        "{%0,%1,%2,%3}, {%4,%5,%6,%7}, {%8,%9}, {%0,%1,%2,%3};"
        : "+f"(d[0]), "+f"(d[1]), "+f"(d[2]), "+f"(d[3])
        : "r"(a0), "r"(a1), "r"(a2), "r"(a3), "r"(b0), "r"(b1));
}
// D = A*B + {cx,cy,cx,cy}
__device__ __forceinline__ void mma16c(float* d, uint32_t a0, uint32_t a1,
                                       uint32_t a2, uint32_t a3,
                                       uint32_t b0, uint32_t b1,
                                       float cx, float cy) {
    asm volatile(
        "mma.sync.aligned.m16n8k16.row.col.f32.f16.f16.f32 "
        "{%0,%1,%2,%3}, {%4,%5,%6,%7}, {%8,%9}, {%10,%11,%10,%11};"
        : "=f"(d[0]), "=f"(d[1]), "=f"(d[2]), "=f"(d[3])
        : "r"(a0), "r"(a1), "r"(a2), "r"(a3), "r"(b0), "r"(b1),
          "f"(cx), "f"(cy));
}

__global__ __launch_bounds__(NTHREADS, 2) void edge_net_mma(
    const float* __restrict__ states,
    const float* __restrict__ edges,
    const float* __restrict__ bg,
    float* __restrict__ out)
{
    extern __shared__ char sm[];
    uint4*  EHL = (uint4*)(sm + SM_EHL);     // [row][q]
    float2* SP  = (float2*)(sm + SM_SP);     // [a][row][q2]
    float*  OSM = (float*)(sm + SM_OSM);     // [row][il][q], pitch 68

    const int tid = threadIdx.x;
    const int eb = blockIdx.x & 511;         // edge block (128 edges)
    const int cb = blockIdx.x >> 9;          // column half (512 cols)
    const int gbase = eb * 128;
    const int col0 = cb * 512;

    const int w = tid >> 5, lane = tid & 31;
    const int g = lane >> 2;                 // groupID: row-in-tile / B-col
    const int q = lane & 3;                  // threadID-in-group

    // ---- Stage + split edges ----
    {
        const float2* er = (const float2*)(edges + (size_t)gbase * 16);
        #pragma unroll
        for (int k = 0; k < 2; k++) {
            int item = tid + k * 256;        // 0..511 over [row][q]
            int row = item >> 2, qq = item & 3;
            float2 v0 = er[row * 8 + qq];
            float2 v1 = er[row * 8 + qq + 4];
            __half h0, l0, h1, l1, h2v, l2, h3, l3;
            split16(v0.x, h0, l0);  split16(v0.y, h1, l1);
            split16(v1.x, h2v, l2); split16(v1.y, h3, l3);
            EHL[item] = make_uint4(pack_h2(h0, h1), pack_h2(h2v, h3),
                                   pack_h2(l0, l1), pack_h2(l2, l3));
        }
    }
    // ---- Stage states: SP[a][row][q2] = {s[row][8a+2q2], s[row][8a+2q2+1]} ----
    {
        const float4* sv = (const float4*)(states + (size_t)gbase * 32);
        #pragma unroll
        for (int k = 0; k < 4; k++) {
            int idx = tid + k * 256;         // 0..1023 over [row][f4]
            int row = idx >> 3, f4 = idx & 7;
            float4 v = sv[idx];
            int a = f4 >> 1, q2 = (f4 & 1) * 2;
            *(float4*)((float*)SP + ((a * 128 + row) * 4 + q2) * 2) = v;
        }
    }
    __syncthreads();

    // ---- W + bias fragments -> registers (after sync) ----
    uint4 whl[8];
    float2 b2[8];
    #pragma unroll
    for (int ct = 0; ct < 8; ct++) {
        int n = col0 + w * 64 + ct * 8 + g;
        whl[ct] = d_Whl[n * 4 + q];
        b2[ct] = *(const float2*)(bg + col0 + w * 64 + ct * 8 + 2 * q);
    }

    // ---- Main: 8 rolled steps of 16 rows ----
    #pragma unroll 1
    for (int hp = 0; hp < 8; hp++) {
        const int rb = hp * 16;

        const uint4 aA = EHL[(rb + g) * 4 + q];       // rows g
        const uint4 aB = EHL[(rb + 8 + g) * 4 + q];   // rows g+8

        float mm[2][2] = {{0.f, 0.f}, {0.f, 0.f}};    // [ip][row-half]

        #pragma unroll
        for (int a = 0; a < 4; a++) {
            const float2 s0 = SP[a * 512 + (rb + g) * 4 + q];
            const float2 s1 = SP[a * 512 + (rb + 8 + g) * 4 + q];

            #pragma unroll
            for (int ip = 0; ip < 2; ip++) {
                const int ct = ip * 4 + a;
                float d[4];
                mma16c(d, aA.x, aB.x, aA.y, aB.y, whl[ct].x, whl[ct].y,
                       b2[ct].x, b2[ct].y);
                mma16 (d, aA.x, aB.x, aA.y, aB.y, whl[ct].z, whl[ct].w);
                mma16 (d, aA.z, aB.z, aA.w, aB.w, whl[ct].x, whl[ct].y);

                mm[ip][0] = fmaf(fmaxf(d[0], 0.f), s0.x, mm[ip][0]);
                mm[ip][0] = fmaf(fmaxf(d[1], 0.f), s0.y, mm[ip][0]);
                mm[ip][1] = fmaf(fmaxf(d[2], 0.f), s1.x, mm[ip][1]);
                mm[ip][1] = fmaf(fmaxf(d[3], 0.f), s1.y, mm[ip][1]);
            }
        }

        // ---- Store quad partials (fire-and-forget, conflict-free: bank=4g+q) ----
        #pragma unroll
        for (int ip = 0; ip < 2; ip++) {
            const int il = w * 2 + ip;       // local column 0..15
            OSM[(rb + g) * 68 + il * 4 + q]     = mm[ip][0];
            OSM[(rb + 8 + g) * 68 + il * 4 + q] = mm[ip][1];
        }
    }

    // ---- Flush: sum 4 partials per output, coalesced STG ----
    __syncthreads();
    #pragma unroll
    for (int k = 0; k < 8; k++) {
        int idx = tid + k * 256;             // 0..2047 over [row][il]
        int row = idx >> 4, il = idx & 15;
        float4 p = *(const float4*)(OSM + row * 68 + il * 4);
        out[(size_t)(gbase + row) * 32 + cb * 16 + il] =
            (p.x + p.y) + (p.z + p.w);
    }
}

extern "C" void kernel_launch(void* const* d_in, const int* in_sizes, int n_in,
                              void* d_out, int out_size)
{
    const float* states = (const float*)d_in[0];  // [16, 4096, 32]
    const float* edges  = (const float*)d_in[1];  // [16, 4096, 16]
    const float* W      = (const float*)d_in[2];  // [16, 1024]
    const float* b      = (const float*)d_in[3];  // [1024]
    float* out          = (float*)d_out;          // [16, 4096, 32]

    (void)in_sizes; (void)n_in; (void)out_size;

    static int configured = 0;
    if (!configured) {
        cudaFuncSetAttribute(edge_net_mma,
                             cudaFuncAttributeMaxDynamicSharedMemorySize, SM_TOTAL);
        configured = 1;
    }
    prep_w<<<16, 256>>>(W);
    edge_net_mma<<<1024, NTHREADS, SM_TOTAL>>>(states, edges, b, out);
}

// round 14
// speedup vs baseline: 1.5021x; 1.3255x over previous
#include <cuda_runtime.h>
#include <cuda_fp16.h>
#include <cstdint>

// EdgeNetwork via single-piece fp16 mma.sync m16n8k16.
// H = E@W + b ; messages[g,i] = sum_j relu(H[g, 32i+j]) * s[g,j]
// E, W rounded to fp16 (rel err ~2.4e-4 << 1e-3 threshold); accum + epilogue fp32.
// R14: 1 mma/tile, W+bias in regs (~32), 3 CTAs/SM, OSM quad-partial reduce.

#define NTHREADS 256

// dynamic smem offsets (bytes)
#define SM_EH   0                        // uint2[512]           4 KB
#define SM_SP   4096                     // float2[2048]        16 KB
#define SM_OSM  20480                    // float[128*68]    34816 B
#define SM_TOTAL (20480 + 34816)         // 55296 B/CTA (x3 = 162 KB/SM)

// fp16 W, fragment-permuted:
// d_Wh[n*4+q] = { h2(w[2q][n],w[2q+1][n]), h2(w[2q+8][n],w[2q+9][n]) }
__device__ uint2 d_Wh[4096];

__device__ __forceinline__ uint32_t pack_h2f(float a, float b) {
    __half2 h = __floats2half2_rn(a, b);
    return *reinterpret_cast<uint32_t*>(&h);
}

__global__ void prep_w(const float* __restrict__ W) {
    int idx = blockIdx.x * 256 + threadIdx.x;   // 0..4095 over [n][q]
    int n = idx >> 2, q = idx & 3;
    d_Wh[idx] = make_uint2(
        pack_h2f(W[(2 * q)     * 1024 + n], W[(2 * q + 1) * 1024 + n]),
        pack_h2f(W[(2 * q + 8) * 1024 + n], W[(2 * q + 9) * 1024 + n]));
}

// D = A*B + {cx,cy,cx,cy}
__device__ __forceinline__ void mma16c(float* d, uint32_t a0, uint32_t a1,
                                       uint32_t a2, uint32_t a3,
                                       uint32_t b0, uint32_t b1,
                                       float cx, float cy) {
    asm volatile(
        "mma.sync.aligned.m16n8k16.row.col.f32.f16.f16.f32 "
        "{%0,%1,%2,%3}, {%4,%5,%6,%7}, {%8,%9}, {%10,%11,%10,%11};"
        : "=f"(d[0]), "=f"(d[1]), "=f"(d[2]), "=f"(d[3])
        : "r"(a0), "r"(a1), "r"(a2), "r"(a3), "r"(b0), "r"(b1),
          "f"(cx), "f"(cy));
}

__global__ __launch_bounds__(NTHREADS, 3) void edge_net_mma(
    const float* __restrict__ states,
    const float* __restrict__ edges,
    const float* __restrict__ bg,
    float* __restrict__ out)
{
    extern __shared__ char sm[];
    uint2*  EH  = (uint2*)(sm + SM_EH);      // [row][q]
    float2* SP  = (float2*)(sm + SM_SP);     // [a][row][q2]
    float*  OSM = (float*)(sm + SM_OSM);     // [row][il][q], pitch 68

    const int tid = threadIdx.x;
    const int eb = blockIdx.x & 511;         // edge block (128 edges)
    const int cb = blockIdx.x >> 9;          // column half (512 cols)
    const int gbase = eb * 128;
    const int col0 = cb * 512;

    const int w = tid >> 5, lane = tid & 31;
    const int g = lane >> 2;                 // groupID: row-in-tile / B-col
    const int q = lane & 3;                  // threadID-in-group

    // ---- Stage edges as fp16 fragments ----
    {
        const float2* er = (const float2*)(edges + (size_t)gbase * 16);
        #pragma unroll
        for (int k = 0; k < 2; k++) {
            int item = tid + k * 256;        // 0..511 over [row][q]
            int row = item >> 2, qq = item & 3;
            float2 v0 = er[row * 8 + qq];
            float2 v1 = er[row * 8 + qq + 4];
            EH[item] = make_uint2(pack_h2f(v0.x, v0.y), pack_h2f(v1.x, v1.y));
        }
    }
    // ---- Stage states: SP[a][row][q2] = {s[row][8a+2q2], s[row][8a+2q2+1]} ----
    {
        const float4* sv = (const float4*)(states + (size_t)gbase * 32);
        #pragma unroll
        for (int k = 0; k < 4; k++) {
            int idx = tid + k * 256;         // 0..1023 over [row][f4]
            int row = idx >> 3, f4 = idx & 7;
            float4 v = sv[idx];
            int a = f4 >> 1, q2 = (f4 & 1) * 2;
            *(float4*)((float*)SP + ((a * 128 + row) * 4 + q2) * 2) = v;
        }
    }
    __syncthreads();

    // ---- W + bias fragments -> registers (after sync) ----
    uint2 wh[8];
    float2 b2[8];
    #pragma unroll
    for (int ct = 0; ct < 8; ct++) {
        int n = col0 + w * 64 + ct * 8 + g;
        wh[ct] = d_Wh[n * 4 + q];
        b2[ct] = *(const float2*)(bg + col0 + w * 64 + ct * 8 + 2 * q);
    }

    // ---- Main: 8 rolled steps of 16 rows ----
    #pragma unroll 1
    for (int hp = 0; hp < 8; hp++) {
        const int rb = hp * 16;

        const uint2 aA = EH[(rb + g) * 4 + q];        // rows g
        const uint2 aB = EH[(rb + 8 + g) * 4 + q];    // rows g+8

        float mm[2][2] = {{0.f, 0.f}, {0.f, 0.f}};    // [ip][row-half]

        #pragma unroll
        for (int a = 0; a < 4; a++) {
            const float2 s0 = SP[a * 512 + (rb + g) * 4 + q];
            const float2 s1 = SP[a * 512 + (rb + 8 + g) * 4 + q];

            #pragma unroll
            for (int ip = 0; ip < 2; ip++) {
                const int ct = ip * 4 + a;
                float d[4];
                mma16c(d, aA.x, aB.x, aA.y, aB.y, wh[ct].x, wh[ct].y,
                       b2[ct].x, b2[ct].y);

                mm[ip][0] = fmaf(fmaxf(d[0], 0.f), s0.x, mm[ip][0]);
                mm[ip][0] = fmaf(fmaxf(d[1], 0.f), s0.y, mm[ip][0]);
                mm[ip][1] = fmaf(fmaxf(d[2], 0.f), s1.x, mm[ip][1]);
                mm[ip][1] = fmaf(fmaxf(d[3], 0.f), s1.y, mm[ip][1]);
            }
        }

        // ---- Store quad partials (conflict-free: bank = 4g+q) ----
        #pragma unroll
        for (int ip = 0; ip < 2; ip++) {
            const int il = w * 2 + ip;       // local column 0..15
            OSM[(rb + g) * 68 + il * 4 + q]     = mm[ip][0];
            OSM[(rb + 8 + g) * 68 + il * 4 + q] = mm[ip][1];
        }
    }

    // ---- Flush: sum 4 partials per output, coalesced STG ----
    __syncthreads();
    #pragma unroll
    for (int k = 0; k < 8; k++) {
        int idx = tid + k * 256;             // 0..2047 over [row][il]
        int row = idx >> 4, il = idx & 15;
        float4 p = *(const float4*)(OSM + row * 68 + il * 4);
        out[(size_t)(gbase + row) * 32 + cb * 16 + il] =
            (p.x + p.y) + (p.z + p.w);
    }
}

extern "C" void kernel_launch(void* const* d_in, const int* in_sizes, int n_in,
                              void* d_out, int out_size)
{
    const float* states = (const float*)d_in[0];  // [16, 4096, 32]
    const float* edges  = (const float*)d_in[1];  // [16, 4096, 16]
    const float* W      = (const float*)d_in[2];  // [16, 1024]
    const float* b      = (const float*)d_in[3];  // [1024]
    float* out          = (float*)d_out;          // [16, 4096, 32]

    (void)in_sizes; (void)n_in; (void)out_size;

    static int configured = 0;
    if (!configured) {
        cudaFuncSetAttribute(edge_net_mma,
                             cudaFuncAttributeMaxDynamicSharedMemorySize, SM_TOTAL);
        configured = 1;
    }
    prep_w<<<16, 256>>>(W);
    edge_net_mma<<<1024, NTHREADS, SM_TOTAL>>>(states, edges, b, out);
}